// round 12
// baseline (speedup 1.0000x reference)
#include <cuda_runtime.h>
#include <cuda_bf16.h>
#include <cuda_fp16.h>
#include <math.h>
#include <stdint.h>

#define B   2
#define S   4096
#define D   2048
#define HQ  16
#define HKV 4
#define HD  128
#define W   512
#define BS  (B*S)
#define REP (HQ/HKV)
#define NQKV 3072   // HQ*HD + 2*HKV*HD

typedef __nv_bfloat16 bf16;

// ---------------- device globals (no allocation allowed) --------------------
__device__ __align__(128) __half g_xn   [(size_t)BS * D];        // rmsnorm out fp16
__device__ __align__(128) __half g_wqkvt[(size_t)NQKV * D];      // q[0,2048) k[2048,2560) v[2560,3072)
__device__ __align__(128) __half g_wot  [(size_t)D * D];
__device__ __align__(128) __half g_qkvp [(size_t)BS * NQKV];     // fused qkv proj fp16
__device__ __align__(128) __half g_q  [(size_t)B*HQ*S*HD];       // [B,HQ,S,HD] fp16 (pre-scaled)
__device__ __align__(128) __half g_k  [(size_t)B*HKV*S*HD];      // [B,HKV,S,HD] fp16
__device__ __align__(128) __half g_vt [(size_t)B*HKV*HD*S];      // [B,HKV,HD,S] fp16
__device__ __align__(128) __half g_att [(size_t)BS * D];         // attention out fp16
__device__ float g_cos[S * (HD/2)];
__device__ float g_sin[S * (HD/2)];

// ---------------- helpers ----------------------------------------------------
__device__ __forceinline__ uint32_t packh2(float x, float y) {
    __half2 h = __floats2half2_rn(x, y);
    return *(uint32_t*)&h;
}

__device__ __forceinline__ void mma16816h(float* c, const uint32_t* a, uint32_t b0, uint32_t b1) {
    asm volatile(
        "mma.sync.aligned.m16n8k16.row.col.f32.f16.f16.f32 "
        "{%0,%1,%2,%3}, {%4,%5,%6,%7}, {%8,%9}, {%0,%1,%2,%3};\n"
        : "+f"(c[0]), "+f"(c[1]), "+f"(c[2]), "+f"(c[3])
        : "r"(a[0]), "r"(a[1]), "r"(a[2]), "r"(a[3]), "r"(b0), "r"(b1));
}

__device__ __forceinline__ uint32_t smem_u32(const void* p) {
    return (uint32_t)__cvta_generic_to_shared(p);
}

__device__ __forceinline__ void ldsm4(uint32_t* r, uint32_t addr) {
    asm volatile("ldmatrix.sync.aligned.m8n8.x4.shared.b16 {%0,%1,%2,%3}, [%4];"
                 : "=r"(r[0]), "=r"(r[1]), "=r"(r[2]), "=r"(r[3]) : "r"(addr));
}

#define CP16(dst, src) \
    asm volatile("cp.async.cg.shared.global [%0], [%1], 16;" :: "r"(dst), "l"(src))
#define CP_COMMIT()  asm volatile("cp.async.commit_group;")
#define CP_WAIT(n)   asm volatile("cp.async.wait_group %0;" :: "n"(n))

// ---------------- RoPE tables (fp64) -----------------------------------------
__global__ void rope_table_kernel() {
    int pos = blockIdx.x;
    int i   = threadIdx.x;                 // 0..63
    double inv = pow(10000.0, -(double)i / 64.0);
    double f   = (double)pos * inv;
    g_cos[pos * 64 + i] = (float)cos(f);
    g_sin[pos * 64 + i] = (float)sin(f);
}

// ---------------- RMSNorm -> fp16 ---------------------------------------------
__global__ void rmsnorm_kernel(const float* __restrict__ x,
                               const float* __restrict__ g) {
    int row = blockIdx.x;
    int tid = threadIdx.x;                 // 256
    const float4* xr = (const float4*)(x + (size_t)row * D);
    float4 v0 = xr[tid];
    float4 v1 = xr[tid + 256];
    float ss = v0.x*v0.x + v0.y*v0.y + v0.z*v0.z + v0.w*v0.w
             + v1.x*v1.x + v1.y*v1.y + v1.z*v1.z + v1.w*v1.w;
    #pragma unroll
    for (int o = 16; o; o >>= 1) ss += __shfl_xor_sync(0xffffffffu, ss, o);
    __shared__ float red[8];
    __shared__ float s_inv;
    if ((tid & 31) == 0) red[tid >> 5] = ss;
    __syncthreads();
    if (tid == 0) {
        float t = 0.f;
        #pragma unroll
        for (int i = 0; i < 8; i++) t += red[i];
        s_inv = 1.0f / sqrtf(t / (float)D + 1e-6f);
    }
    __syncthreads();
    float inv = s_inv;
    const float4* gg = (const float4*)g;
    float4 g0 = gg[tid], g1 = gg[tid + 256];
    size_t base = (size_t)row * D;
    __half2* oh = (__half2*)(g_xn + base);
    oh[2*tid]       = __floats2half2_rn(v0.x*inv*g0.x, v0.y*inv*g0.y);
    oh[2*tid + 1]   = __floats2half2_rn(v0.z*inv*g0.z, v0.w*inv*g0.w);
    oh[2*(tid+256)]   = __floats2half2_rn(v1.x*inv*g1.x, v1.y*inv*g1.y);
    oh[2*(tid+256)+1] = __floats2half2_rn(v1.z*inv*g1.z, v1.w*inv*g1.w);
}

// ---------------- fused weight transpose -> fp16 (wq|wk|wv) -------------------
__global__ void wconv_qkv_kernel(const float* __restrict__ wq,
                                 const float* __restrict__ wk,
                                 const float* __restrict__ wv) {
    __shared__ float tile[32][33];
    int n0 = blockIdx.x * 32, k0 = blockIdx.y * 32;
    const float* src;
    int scol, sN;
    if (n0 < 2048)      { src = wq; scol = n0;        sN = 2048; }
    else if (n0 < 2560) { src = wk; scol = n0 - 2048; sN = 512;  }
    else                { src = wv; scol = n0 - 2560; sN = 512;  }
    int tx = threadIdx.x, ty = threadIdx.y;      // (32,8)
    #pragma unroll
    for (int i = 0; i < 4; i++)
        tile[ty + 8*i][tx] = src[(size_t)(k0 + ty + 8*i) * sN + scol + tx];
    __syncthreads();
    #pragma unroll
    for (int i = 0; i < 4; i++)
        g_wqkvt[(size_t)(n0 + ty + 8*i) * D + k0 + tx] = __float2half(tile[tx][ty + 8*i]);
}

// ---------------- single weight transpose -> fp16 -----------------------------
__global__ void wconv_kernel(const float* __restrict__ Wsrc,
                             __half* __restrict__ T, int K, int N) {
    __shared__ float tile[32][33];
    int n0 = blockIdx.x * 32, k0 = blockIdx.y * 32;
    int tx = threadIdx.x, ty = threadIdx.y;      // (32,8)
    #pragma unroll
    for (int i = 0; i < 4; i++)
        tile[ty + 8*i][tx] = Wsrc[(size_t)(k0 + ty + 8*i) * N + n0 + tx];
    __syncthreads();
    #pragma unroll
    for (int i = 0; i < 4; i++)
        T[(size_t)(n0 + ty + 8*i) * K + k0 + tx] = __float2half(tile[tx][ty + 8*i]);
}

// ---------------- fp16 GEMM: C[M,N] = A @ Bt^T, 3-stage pipeline --------------
// __launch_bounds__(256, 3): cap regs at 85 so 3 CTAs/SM fit (occupancy was the
// binding constraint: tensor=41.8%, occ=24%, issue=16% at 2 CTAs/SM).
#define APAD 40
#define GSTG 10240   // bytes per (stage, matrix) buffer: 128*APAD*2
template <bool OUT_FP16>
__global__ void __launch_bounds__(256, 3)
gemm_f16(const __half* __restrict__ A, const __half* __restrict__ Bt,
         void* __restrict__ Cv, int N, int K) {
    extern __shared__ __half dsm[];
    int tid  = threadIdx.x;
    int m0   = blockIdx.y * 128, n0 = blockIdx.x * 128;
    int warp = tid >> 5, lane = tid & 31;
    int mw   = (warp >> 1) * 32, nw = (warp & 1) * 64;

    float acc[2][8][4];
    #pragma unroll
    for (int a = 0; a < 2; a++)
        #pragma unroll
        for (int b = 0; b < 8; b++)
            #pragma unroll
            for (int c = 0; c < 4; c++) acc[a][b][c] = 0.f;

    int row = tid >> 1, hf = tid & 1;
    const __half* pA = A  + (size_t)(m0 + row) * K + hf * 16;
    const __half* pB = Bt + (size_t)(n0 + row) * K + hf * 16;

    uint32_t sm_base = smem_u32(dsm);
    uint32_t s_off   = (uint32_t)((row * APAD + hf * 16) * 2);

    int g = lane >> 3;
    uint32_t a_frag_off = (uint32_t)((((g & 1) * 8 + (lane & 7)) * APAD + (g >> 1) * 8) * 2);
    uint32_t b_frag_off = (uint32_t)((((g >> 1) * 8 + (lane & 7)) * APAD + (g & 1) * 8) * 2);

#define GEMM_ISSUE(st, k0v) do {                                          \
    uint32_t dA = sm_base + (st) * (2 * GSTG) + s_off;                    \
    uint32_t dB = dA + GSTG;                                              \
    CP16(dA,      pA + (k0v)); CP16(dA + 16, pA + (k0v) + 8);             \
    CP16(dB,      pB + (k0v)); CP16(dB + 16, pB + (k0v) + 8);             \
    CP_COMMIT();                                                          \
} while (0)

    int nIter = K / 32;
    GEMM_ISSUE(0, 0);
    GEMM_ISSUE(1, 32);
    for (int i = 0; i < nIter; i++) {
        if (i + 1 < nIter) { CP_WAIT(1); } else { CP_WAIT(0); }
        __syncthreads();
        if (i + 2 < nIter)
            GEMM_ISSUE((i + 2) % 3, (i + 2) * 32);

        int st = i % 3;
        uint32_t aB = sm_base + st * (2 * GSTG);
        uint32_t bB = aB + GSTG;
        #pragma unroll
        for (int kk = 0; kk < 32; kk += 16) {
            uint32_t af[2][4];
            #pragma unroll
            for (int mt = 0; mt < 2; mt++)
                ldsm4(af[mt], aB + (uint32_t)(((mw + mt*16) * APAD + kk) * 2) + a_frag_off);
            #pragma unroll
            for (int nt16 = 0; nt16 < 4; nt16++) {
                uint32_t bb[4];
                ldsm4(bb, bB + (uint32_t)(((nw + nt16*16) * APAD + kk) * 2) + b_frag_off);
                #pragma unroll
                for (int mt = 0; mt < 2; mt++) {
                    mma16816h(acc[mt][2*nt16],     af[mt], bb[0], bb[1]);
                    mma16816h(acc[mt][2*nt16 + 1], af[mt], bb[2], bb[3]);
                }
            }
        }
    }

    #pragma unroll
    for (int mt = 0; mt < 2; mt++)
        #pragma unroll
        for (int nt = 0; nt < 8; nt++) {
            size_t r0 = (size_t)(m0 + mw + mt*16 + (lane>>2)) * N
                      + n0 + nw + nt*8 + (lane&3)*2;
            if (OUT_FP16) {
                __half* C = (__half*)Cv;
                *(__half2*)(C + r0) = __floats2half2_rn(acc[mt][nt][0], acc[mt][nt][1]);
                *(__half2*)(C + r0 + (size_t)8*N) = __floats2half2_rn(acc[mt][nt][2], acc[mt][nt][3]);
            } else {
                float* C = (float*)Cv;
                *(float2*)(C + r0) = make_float2(acc[mt][nt][0], acc[mt][nt][1]);
                *(float2*)(C + r0 + (size_t)8*N) = make_float2(acc[mt][nt][2], acc[mt][nt][3]);
            }
        }
}

// ---------------- RoPE + layout (reads fp16 fused qkv proj) ------------------
__global__ void rope_q_kernel() {
    int bs = blockIdx.x;
    int b  = bs / S, s = bs % S;
    const float QSCALE = (float)(0.08838834764831843 * 1.4426950408889634);
    for (int p = threadIdx.x; p < HQ * 64; p += 256) {
        int h = p >> 6, i = p & 63;
        float c  = g_cos[s * 64 + i];
        float sn = g_sin[s * 64 + i];
        float2 v = __half22float2(*(const __half2*)(g_qkvp + (size_t)bs * NQKV + h * HD + 2 * i));
        float ox = (v.x * c - v.y * sn) * QSCALE;
        float oy = (v.x * sn + v.y * c) * QSCALE;
        size_t off = (((size_t)(b * HQ + h)) * S + s) * HD + 2 * i;
        *(uint32_t*)(g_q + off) = packh2(ox, oy);
    }
}
__global__ void rope_k_kernel() {
    int bs = blockIdx.x;
    int b  = bs / S, s = bs % S;
    int p  = threadIdx.x;                   // 256 = HKV*64
    int h = p >> 6, i = p & 63;
    float c  = g_cos[s * 64 + i];
    float sn = g_sin[s * 64 + i];
    float2 v = __half22float2(*(const __half2*)(g_qkvp + (size_t)bs * NQKV + 2048 + h * HD + 2 * i));
    float ox = v.x * c - v.y * sn;
    float oy = v.x * sn + v.y * c;
    size_t off = (((size_t)(b * HKV + h)) * S + s) * HD + 2 * i;
    *(uint32_t*)(g_k + off) = packh2(ox, oy);
}
__global__ void vtrans_kernel() {
    __shared__ __half t[32][34];
    int s0 = blockIdx.x * 32, d0 = blockIdx.y * 32, bh = blockIdx.z;
    int b = bh / HKV, hk = bh % HKV;
    int tx = threadIdx.x, ty = threadIdx.y;      // (32,8)
    #pragma unroll
    for (int i = 0; i < 4; i++)
        t[ty + 8*i][tx] = g_qkvp[(size_t)(b * S + s0 + ty + 8*i) * NQKV + 2560 + hk * HD + d0 + tx];
    __syncthreads();
    #pragma unroll
    for (int i = 0; i < 4; i++) {
        size_t off = ((size_t)(b * HKV + hk) * HD + d0 + ty + 8*i) * S + s0 + tx;
        g_vt[off] = t[tx][ty + 8*i];
    }
}

// ---------------- MMA flash attention (all fp16 operands) --------------------
#define QPAD 136
#define VPAD 72
__global__ void __launch_bounds__(128)
attn_kernel() {
    extern __shared__ __half smn[];
    __half* Qs = smn;                  // 64 x QPAD
    __half* Ks = Qs + 64 * QPAD;       // 64 x QPAD
    __half* Vs = Ks + 64 * QPAD;       // 128 x VPAD

    int qb = blockIdx.x, bh = blockIdx.y;
    int b  = bh / HQ, h = bh % HQ;
    int hk = h / REP;
    int qstart = qb * 64;
    int tid = threadIdx.x, warp = tid >> 5, lane = tid & 31;

    uint32_t q_s = smem_u32(Qs);
    uint32_t k_s = smem_u32(Ks);
    uint32_t v_s = smem_u32(Vs);

    // load Q tile (64 x 128 fp16)
    {
        int row = tid >> 1, hf = tid & 1;
        const __half* src = g_q + ((size_t)(b*HQ + h) * S + qstart + row) * HD + hf * 64;
        uint32_t dQ = q_s + (uint32_t)((row * QPAD + hf * 64) * 2);
        #pragma unroll
        for (int j = 0; j < 8; j++)
            CP16(dQ + j*16, src + j*8);
        CP_COMMIT();
    }

    int g = lane >> 3;
    uint32_t a_off  = (uint32_t)((((g&1)*8 + (lane&7)) * QPAD + (g>>1)*8) * 2);
    uint32_t kb_off = (uint32_t)((((g>>1)*8 + (lane&7)) * QPAD + (g&1)*8) * 2);
    uint32_t vb_off = (uint32_t)(((lane&7) * VPAD + g*8) * 2);

    float o[16][4];
    #pragma unroll
    for (int i = 0; i < 16; i++)
        #pragma unroll
        for (int j = 0; j < 4; j++) o[i][j] = 0.f;
    float m0 = -1e30f, m1 = -1e30f, l0 = 0.f, l1 = 0.f;

    int kbeg = qstart - W; if (kbeg < 0) kbeg = 0;
    int kend = qstart + 64;
    const __half* Kg = g_k  + (size_t)(b*HKV + hk) * S * HD;
    const __half* Vg = g_vt + (size_t)(b*HKV + hk) * HD * S;

    int qrow0 = qstart + warp * 16 + (lane >> 2);

    for (int ks = kbeg; ks < kend; ks += 64) {
        __syncthreads();
        {   // K chunk (64 x 128 fp16) + V^T chunk (128 x 64 fp16) via cp.async
            int row = tid >> 1, hf = tid & 1;
            const __half* sK = Kg + (size_t)(ks + row) * HD + hf * 64;
            uint32_t dK = k_s + (uint32_t)((row * QPAD + hf * 64) * 2);
            #pragma unroll
            for (int j = 0; j < 8; j++)
                CP16(dK + j*16, sK + j*8);
            const __half* vS = Vg + (size_t)tid * S + ks;
            uint32_t eV = v_s + (uint32_t)(tid * VPAD * 2);
            #pragma unroll
            for (int j = 0; j < 8; j++)
                CP16(eV + j*16, vS + j*8);
            CP_COMMIT();
            CP_WAIT(0);
        }
        __syncthreads();

        // ---- scores = Q @ K^T (fp16 in, fp32 acc) ----
        float sc[8][4];
        #pragma unroll
        for (int nt = 0; nt < 8; nt++)
            #pragma unroll
            for (int e = 0; e < 4; e++) sc[nt][e] = 0.f;

        #pragma unroll
        for (int kk = 0; kk < 8; kk++) {
            uint32_t aF[4];
            ldsm4(aF, q_s + (uint32_t)((warp*16*QPAD + kk*16) * 2) + a_off);
            #pragma unroll
            for (int nt16 = 0; nt16 < 4; nt16++) {
                uint32_t bb[4];
                ldsm4(bb, k_s + (uint32_t)((nt16*16*QPAD + kk*16) * 2) + kb_off);
                mma16816h(sc[2*nt16],     aF, bb[0], bb[1]);
                mma16816h(sc[2*nt16 + 1], aF, bb[2], bb[3]);
            }
        }

        // ---- mask + online softmax (log2 domain; Q pre-scaled) ----
        #pragma unroll
        for (int nt = 0; nt < 8; nt++)
            #pragma unroll
            for (int e = 0; e < 4; e++) {
                int kp = ks + nt*8 + (lane & 3) * 2 + (e & 1);
                int qr = qrow0 + ((e >= 2) ? 8 : 0);
                if (kp < qr - W || kp > qr) sc[nt][e] = -1e30f;
            }
        float mx0 = -1e30f, mx1 = -1e30f;
        #pragma unroll
        for (int nt = 0; nt < 8; nt++) {
            mx0 = fmaxf(mx0, fmaxf(sc[nt][0], sc[nt][1]));
            mx1 = fmaxf(mx1, fmaxf(sc[nt][2], sc[nt][3]));
        }
        mx0 = fmaxf(mx0, __shfl_xor_sync(0xffffffffu, mx0, 1));
        mx0 = fmaxf(mx0, __shfl_xor_sync(0xffffffffu, mx0, 2));
        mx1 = fmaxf(mx1, __shfl_xor_sync(0xffffffffu, mx1, 1));
        mx1 = fmaxf(mx1, __shfl_xor_sync(0xffffffffu, mx1, 2));
        float mn0 = fmaxf(m0, mx0), mn1 = fmaxf(m1, mx1);
        float a0 = exp2f(m0 - mn0), a1 = exp2f(m1 - mn1);
        m0 = mn0; m1 = mn1;
        float s0 = 0.f, s1 = 0.f;
        #pragma unroll
        for (int nt = 0; nt < 8; nt++) {
            sc[nt][0] = exp2f(sc[nt][0] - mn0);
            sc[nt][1] = exp2f(sc[nt][1] - mn0);
            sc[nt][2] = exp2f(sc[nt][2] - mn1);
            sc[nt][3] = exp2f(sc[nt][3] - mn1);
            s0 += sc[nt][0] + sc[nt][1];
            s1 += sc[nt][2] + sc[nt][3];
        }
        s0 += __shfl_xor_sync(0xffffffffu, s0, 1);
        s0 += __shfl_xor_sync(0xffffffffu, s0, 2);
        s1 += __shfl_xor_sync(0xffffffffu, s1, 1);
        s1 += __shfl_xor_sync(0xffffffffu, s1, 2);
        l0 = l0 * a0 + s0;
        l1 = l1 * a1 + s1;
        #pragma unroll
        for (int dt = 0; dt < 16; dt++) {
            o[dt][0] *= a0; o[dt][1] *= a0;
            o[dt][2] *= a1; o[dt][3] *= a1;
        }

        // ---- O += P @ V (P fp16, V fp16) ----
        #pragma unroll
        for (int k2 = 0; k2 < 2; k2++) {
            uint32_t pF[2][4];
            #pragma unroll
            for (int q8 = 0; q8 < 2; q8++) {
                int nt = k2 * 4 + q8 * 2;
                pF[q8][0] = packh2(sc[nt][0],   sc[nt][1]);
                pF[q8][1] = packh2(sc[nt][2],   sc[nt][3]);
                pF[q8][2] = packh2(sc[nt+1][0], sc[nt+1][1]);
                pF[q8][3] = packh2(sc[nt+1][2], sc[nt+1][3]);
            }
            #pragma unroll
            for (int dt = 0; dt < 16; dt++) {
                uint32_t vv[4];
                ldsm4(vv, v_s + (uint32_t)((dt*8*VPAD + k2*32) * 2) + vb_off);
                mma16816h(o[dt], pF[0], vv[0], vv[1]);
                mma16816h(o[dt], pF[1], vv[2], vv[3]);
            }
        }
    }

    // ---- finalize, write fp16 attention output ------------------------------
    float inv0 = 1.f / l0, inv1 = 1.f / l1;
    #pragma unroll
    for (int dt = 0; dt < 16; dt++) {
        int d = dt * 8 + (lane & 3) * 2;
        size_t off0 = (size_t)(b * S + qrow0)     * D + h * HD + d;
        size_t off1 = (size_t)(b * S + qrow0 + 8) * D + h * HD + d;
        *(__half2*)(g_att + off0) = __floats2half2_rn(o[dt][0] * inv0, o[dt][1] * inv0);
        *(__half2*)(g_att + off1) = __floats2half2_rn(o[dt][2] * inv1, o[dt][3] * inv1);
    }
}

// ---------------- launch -------------------------------------------------------
extern "C" void kernel_launch(void* const* d_in, const int* in_sizes, int n_in,
                              void* d_out, int out_size) {
    const float* x  = (const float*)d_in[0];
    const float* g  = (const float*)d_in[1];
    const float* wq = (const float*)d_in[2];
    const float* wk = (const float*)d_in[3];
    const float* wv = (const float*)d_in[4];
    const float* wo = (const float*)d_in[5];
    float* out = (float*)d_out;

    void *xn, *wqkv, *wot, *qkvp, *att;
    cudaGetSymbolAddress(&xn, g_xn);
    cudaGetSymbolAddress(&wqkv, g_wqkvt);
    cudaGetSymbolAddress(&wot, g_wot);
    cudaGetSymbolAddress(&qkvp, g_qkvp);
    cudaGetSymbolAddress(&att, g_att);

    const int gemm_smem = 6 * GSTG;   // 61440 bytes (3 stages x A,B)
    cudaFuncSetAttribute(gemm_f16<true>,
                         cudaFuncAttributeMaxDynamicSharedMemorySize, gemm_smem);
    cudaFuncSetAttribute(gemm_f16<false>,
                         cudaFuncAttributeMaxDynamicSharedMemorySize, gemm_smem);
    const int attn_smem = (2 * 64 * QPAD + 128 * VPAD) * (int)sizeof(__half);  // 53248
    cudaFuncSetAttribute(attn_kernel,
                         cudaFuncAttributeMaxDynamicSharedMemorySize, attn_smem);

    // Launch order: profiler captures launch #4 -> QKV GEMM there.
    wconv_qkv_kernel<<<dim3(NQKV/32, D/32), dim3(32, 8)>>>(wq, wk, wv);        // 1
    rmsnorm_kernel<<<BS, 256>>>(x, g);                                         // 2
    rope_table_kernel<<<S, 64>>>();                                            // 3

    gemm_f16<true><<<dim3(NQKV/128, BS/128), 256, gemm_smem>>>(                // 4 <-- ncu
        (const __half*)xn, (const __half*)wqkv, qkvp, NQKV, D);

    wconv_kernel<<<dim3(D/32, D/32), dim3(32, 8)>>>(wo, (__half*)wot, D, D);   // 5
    rope_q_kernel<<<BS, 256>>>();                                              // 6
    rope_k_kernel<<<BS, 256>>>();                                              // 7
    vtrans_kernel<<<dim3(S/32, HD/32, B*HKV), dim3(32, 8)>>>();                // 8
    attn_kernel<<<dim3(S/64, B*HQ), 128, attn_smem>>>();                       // 9
    gemm_f16<false><<<dim3(D/128, BS/128), 256, gemm_smem>>>(                  // 10
        (const __half*)att, (const __half*)wot, out, D, D);
}

// round 13
// speedup vs baseline: 1.3192x; 1.3192x over previous
#include <cuda_runtime.h>
#include <cuda_bf16.h>
#include <cuda_fp16.h>
#include <math.h>
#include <stdint.h>

#define B   2
#define S   4096
#define D   2048
#define HQ  16
#define HKV 4
#define HD  128
#define W   512
#define BS  (B*S)
#define REP (HQ/HKV)
#define NQKV 3072   // HQ*HD + 2*HKV*HD

typedef __nv_bfloat16 bf16;

// ---------------- device globals (no allocation allowed) --------------------
__device__ __align__(128) __half g_xn   [(size_t)BS * D];        // rmsnorm out fp16
__device__ __align__(128) __half g_wqkvt[(size_t)NQKV * D];      // q[0,2048) k[2048,2560) v[2560,3072)
__device__ __align__(128) __half g_wot  [(size_t)D * D];
__device__ __align__(128) __half g_qkvp [(size_t)BS * NQKV];     // fused qkv proj fp16
__device__ __align__(128) __half g_q  [(size_t)B*HQ*S*HD];       // [B,HQ,S,HD] fp16 (pre-scaled)
__device__ __align__(128) __half g_k  [(size_t)B*HKV*S*HD];      // [B,HKV,S,HD] fp16
__device__ __align__(128) __half g_vt [(size_t)B*HKV*HD*S];      // [B,HKV,HD,S] fp16
__device__ __align__(128) __half g_att [(size_t)BS * D];         // attention out fp16
__device__ float g_cos[S * (HD/2)];
__device__ float g_sin[S * (HD/2)];

// ---------------- helpers ----------------------------------------------------
__device__ __forceinline__ uint32_t packh2(float x, float y) {
    __half2 h = __floats2half2_rn(x, y);
    return *(uint32_t*)&h;
}

__device__ __forceinline__ void mma16816h(float* c, const uint32_t* a, uint32_t b0, uint32_t b1) {
    asm volatile(
        "mma.sync.aligned.m16n8k16.row.col.f32.f16.f16.f32 "
        "{%0,%1,%2,%3}, {%4,%5,%6,%7}, {%8,%9}, {%0,%1,%2,%3};\n"
        : "+f"(c[0]), "+f"(c[1]), "+f"(c[2]), "+f"(c[3])
        : "r"(a[0]), "r"(a[1]), "r"(a[2]), "r"(a[3]), "r"(b0), "r"(b1));
}

__device__ __forceinline__ uint32_t smem_u32(const void* p) {
    return (uint32_t)__cvta_generic_to_shared(p);
}

__device__ __forceinline__ void ldsm4(uint32_t* r, uint32_t addr) {
    asm volatile("ldmatrix.sync.aligned.m8n8.x4.shared.b16 {%0,%1,%2,%3}, [%4];"
                 : "=r"(r[0]), "=r"(r[1]), "=r"(r[2]), "=r"(r[3]) : "r"(addr));
}

#define CP16(dst, src) \
    asm volatile("cp.async.cg.shared.global [%0], [%1], 16;" :: "r"(dst), "l"(src))
#define CP_COMMIT()  asm volatile("cp.async.commit_group;")
#define CP_WAIT(n)   asm volatile("cp.async.wait_group %0;" :: "n"(n))

// ---------------- RoPE tables (fp64) -----------------------------------------
__global__ void rope_table_kernel() {
    int pos = blockIdx.x;
    int i   = threadIdx.x;                 // 0..63
    double inv = pow(10000.0, -(double)i / 64.0);
    double f   = (double)pos * inv;
    g_cos[pos * 64 + i] = (float)cos(f);
    g_sin[pos * 64 + i] = (float)sin(f);
}

// ---------------- RMSNorm -> fp16 ---------------------------------------------
__global__ void rmsnorm_kernel(const float* __restrict__ x,
                               const float* __restrict__ g) {
    int row = blockIdx.x;
    int tid = threadIdx.x;                 // 256
    const float4* xr = (const float4*)(x + (size_t)row * D);
    float4 v0 = xr[tid];
    float4 v1 = xr[tid + 256];
    float ss = v0.x*v0.x + v0.y*v0.y + v0.z*v0.z + v0.w*v0.w
             + v1.x*v1.x + v1.y*v1.y + v1.z*v1.z + v1.w*v1.w;
    #pragma unroll
    for (int o = 16; o; o >>= 1) ss += __shfl_xor_sync(0xffffffffu, ss, o);
    __shared__ float red[8];
    __shared__ float s_inv;
    if ((tid & 31) == 0) red[tid >> 5] = ss;
    __syncthreads();
    if (tid == 0) {
        float t = 0.f;
        #pragma unroll
        for (int i = 0; i < 8; i++) t += red[i];
        s_inv = 1.0f / sqrtf(t / (float)D + 1e-6f);
    }
    __syncthreads();
    float inv = s_inv;
    const float4* gg = (const float4*)g;
    float4 g0 = gg[tid], g1 = gg[tid + 256];
    size_t base = (size_t)row * D;
    __half2* oh = (__half2*)(g_xn + base);
    oh[2*tid]       = __floats2half2_rn(v0.x*inv*g0.x, v0.y*inv*g0.y);
    oh[2*tid + 1]   = __floats2half2_rn(v0.z*inv*g0.z, v0.w*inv*g0.w);
    oh[2*(tid+256)]   = __floats2half2_rn(v1.x*inv*g1.x, v1.y*inv*g1.y);
    oh[2*(tid+256)+1] = __floats2half2_rn(v1.z*inv*g1.z, v1.w*inv*g1.w);
}

// ---------------- fused weight transpose -> fp16 (wq|wk|wv) -------------------
__global__ void wconv_qkv_kernel(const float* __restrict__ wq,
                                 const float* __restrict__ wk,
                                 const float* __restrict__ wv) {
    __shared__ float tile[32][33];
    int n0 = blockIdx.x * 32, k0 = blockIdx.y * 32;
    const float* src;
    int scol, sN;
    if (n0 < 2048)      { src = wq; scol = n0;        sN = 2048; }
    else if (n0 < 2560) { src = wk; scol = n0 - 2048; sN = 512;  }
    else                { src = wv; scol = n0 - 2560; sN = 512;  }
    int tx = threadIdx.x, ty = threadIdx.y;      // (32,8)
    #pragma unroll
    for (int i = 0; i < 4; i++)
        tile[ty + 8*i][tx] = src[(size_t)(k0 + ty + 8*i) * sN + scol + tx];
    __syncthreads();
    #pragma unroll
    for (int i = 0; i < 4; i++)
        g_wqkvt[(size_t)(n0 + ty + 8*i) * D + k0 + tx] = __float2half(tile[tx][ty + 8*i]);
}

// ---------------- single weight transpose -> fp16 -----------------------------
__global__ void wconv_kernel(const float* __restrict__ Wsrc,
                             __half* __restrict__ T, int K, int N) {
    __shared__ float tile[32][33];
    int n0 = blockIdx.x * 32, k0 = blockIdx.y * 32;
    int tx = threadIdx.x, ty = threadIdx.y;      // (32,8)
    #pragma unroll
    for (int i = 0; i < 4; i++)
        tile[ty + 8*i][tx] = Wsrc[(size_t)(k0 + ty + 8*i) * N + n0 + tx];
    __syncthreads();
    #pragma unroll
    for (int i = 0; i < 4; i++)
        T[(size_t)(n0 + ty + 8*i) * K + k0 + tx] = __float2half(tile[tx][ty + 8*i]);
}

// ---------------- fp16 GEMM: C[M,N] = A @ Bt^T, 3-stage pipeline --------------
// 2 CTAs/SM (regs<=128). Stage-wide fragment preload: all 12 ldsm4 for a k32
// chunk are issued before the 32-MMA burst, removing the per-nt16 ldsm->MMA
// dependency bubble that capped tensor at 41.8%.
#define APAD 40
#define GSTG 10240   // bytes per (stage, matrix) buffer: 128*APAD*2
template <bool OUT_FP16>
__global__ void __launch_bounds__(256, 2)
gemm_f16(const __half* __restrict__ A, const __half* __restrict__ Bt,
         void* __restrict__ Cv, int N, int K) {
    extern __shared__ __half dsm[];
    int tid  = threadIdx.x;
    int m0   = blockIdx.y * 128, n0 = blockIdx.x * 128;
    int warp = tid >> 5, lane = tid & 31;
    int mw   = (warp >> 1) * 32, nw = (warp & 1) * 64;

    float acc[2][8][4];
    #pragma unroll
    for (int a = 0; a < 2; a++)
        #pragma unroll
        for (int b = 0; b < 8; b++)
            #pragma unroll
            for (int c = 0; c < 4; c++) acc[a][b][c] = 0.f;

    int row = tid >> 1, hf = tid & 1;
    const __half* pA = A  + (size_t)(m0 + row) * K + hf * 16;
    const __half* pB = Bt + (size_t)(n0 + row) * K + hf * 16;

    uint32_t sm_base = smem_u32(dsm);
    uint32_t s_off   = (uint32_t)((row * APAD + hf * 16) * 2);

    int g = lane >> 3;
    uint32_t a_frag_off = (uint32_t)((((g & 1) * 8 + (lane & 7)) * APAD + (g >> 1) * 8) * 2);
    uint32_t b_frag_off = (uint32_t)((((g >> 1) * 8 + (lane & 7)) * APAD + (g & 1) * 8) * 2);

#define GEMM_ISSUE(st, k0v) do {                                          \
    uint32_t dA = sm_base + (st) * (2 * GSTG) + s_off;                    \
    uint32_t dB = dA + GSTG;                                              \
    CP16(dA,      pA + (k0v)); CP16(dA + 16, pA + (k0v) + 8);             \
    CP16(dB,      pB + (k0v)); CP16(dB + 16, pB + (k0v) + 8);             \
    CP_COMMIT();                                                          \
} while (0)

    int nIter = K / 32;
    GEMM_ISSUE(0, 0);
    GEMM_ISSUE(1, 32);
    for (int i = 0; i < nIter; i++) {
        if (i + 1 < nIter) { CP_WAIT(1); } else { CP_WAIT(0); }
        __syncthreads();
        if (i + 2 < nIter)
            GEMM_ISSUE((i + 2) % 3, (i + 2) * 32);

        int st = i % 3;
        uint32_t aB = sm_base + st * (2 * GSTG);
        uint32_t bB = aB + GSTG;

        // ---- stage-wide fragment preload (12 ldsm4, no interleaved MMAs) ----
        uint32_t af[2][2][4];   // [kk-half][mt]
        uint32_t bb[2][4][4];   // [kk-half][nt16]
        #pragma unroll
        for (int kh = 0; kh < 2; kh++) {
            int kk = kh * 16;
            #pragma unroll
            for (int mt = 0; mt < 2; mt++)
                ldsm4(af[kh][mt], aB + (uint32_t)(((mw + mt*16) * APAD + kk) * 2) + a_frag_off);
            #pragma unroll
            for (int nt16 = 0; nt16 < 4; nt16++)
                ldsm4(bb[kh][nt16], bB + (uint32_t)(((nw + nt16*16) * APAD + kk) * 2) + b_frag_off);
        }
        // ---- 32-MMA burst, fully load-independent ----
        #pragma unroll
        for (int kh = 0; kh < 2; kh++)
            #pragma unroll
            for (int nt16 = 0; nt16 < 4; nt16++)
                #pragma unroll
                for (int mt = 0; mt < 2; mt++) {
                    mma16816h(acc[mt][2*nt16],     af[kh][mt], bb[kh][nt16][0], bb[kh][nt16][1]);
                    mma16816h(acc[mt][2*nt16 + 1], af[kh][mt], bb[kh][nt16][2], bb[kh][nt16][3]);
                }
    }

    #pragma unroll
    for (int mt = 0; mt < 2; mt++)
        #pragma unroll
        for (int nt = 0; nt < 8; nt++) {
            size_t r0 = (size_t)(m0 + mw + mt*16 + (lane>>2)) * N
                      + n0 + nw + nt*8 + (lane&3)*2;
            if (OUT_FP16) {
                __half* C = (__half*)Cv;
                *(__half2*)(C + r0) = __floats2half2_rn(acc[mt][nt][0], acc[mt][nt][1]);
                *(__half2*)(C + r0 + (size_t)8*N) = __floats2half2_rn(acc[mt][nt][2], acc[mt][nt][3]);
            } else {
                float* C = (float*)Cv;
                *(float2*)(C + r0) = make_float2(acc[mt][nt][0], acc[mt][nt][1]);
                *(float2*)(C + r0 + (size_t)8*N) = make_float2(acc[mt][nt][2], acc[mt][nt][3]);
            }
        }
}

// ---------------- RoPE + layout (reads fp16 fused qkv proj) ------------------
__global__ void rope_q_kernel() {
    int bs = blockIdx.x;
    int b  = bs / S, s = bs % S;
    const float QSCALE = (float)(0.08838834764831843 * 1.4426950408889634);
    for (int p = threadIdx.x; p < HQ * 64; p += 256) {
        int h = p >> 6, i = p & 63;
        float c  = g_cos[s * 64 + i];
        float sn = g_sin[s * 64 + i];
        float2 v = __half22float2(*(const __half2*)(g_qkvp + (size_t)bs * NQKV + h * HD + 2 * i));
        float ox = (v.x * c - v.y * sn) * QSCALE;
        float oy = (v.x * sn + v.y * c) * QSCALE;
        size_t off = (((size_t)(b * HQ + h)) * S + s) * HD + 2 * i;
        *(uint32_t*)(g_q + off) = packh2(ox, oy);
    }
}
__global__ void rope_k_kernel() {
    int bs = blockIdx.x;
    int b  = bs / S, s = bs % S;
    int p  = threadIdx.x;                   // 256 = HKV*64
    int h = p >> 6, i = p & 63;
    float c  = g_cos[s * 64 + i];
    float sn = g_sin[s * 64 + i];
    float2 v = __half22float2(*(const __half2*)(g_qkvp + (size_t)bs * NQKV + 2048 + h * HD + 2 * i));
    float ox = v.x * c - v.y * sn;
    float oy = v.x * sn + v.y * c;
    size_t off = (((size_t)(b * HKV + h)) * S + s) * HD + 2 * i;
    *(uint32_t*)(g_k + off) = packh2(ox, oy);
}
__global__ void vtrans_kernel() {
    __shared__ __half t[32][34];
    int s0 = blockIdx.x * 32, d0 = blockIdx.y * 32, bh = blockIdx.z;
    int b = bh / HKV, hk = bh % HKV;
    int tx = threadIdx.x, ty = threadIdx.y;      // (32,8)
    #pragma unroll
    for (int i = 0; i < 4; i++)
        t[ty + 8*i][tx] = g_qkvp[(size_t)(b * S + s0 + ty + 8*i) * NQKV + 2560 + hk * HD + d0 + tx];
    __syncthreads();
    #pragma unroll
    for (int i = 0; i < 4; i++) {
        size_t off = ((size_t)(b * HKV + hk) * HD + d0 + ty + 8*i) * S + s0 + tx;
        g_vt[off] = t[tx][ty + 8*i];
    }
}

// ---------------- MMA flash attention (all fp16 operands) --------------------
#define QPAD 136
#define VPAD 72
__global__ void __launch_bounds__(128)
attn_kernel() {
    extern __shared__ __half smn[];
    __half* Qs = smn;                  // 64 x QPAD
    __half* Ks = Qs + 64 * QPAD;       // 64 x QPAD
    __half* Vs = Ks + 64 * QPAD;       // 128 x VPAD

    int qb = blockIdx.x, bh = blockIdx.y;
    int b  = bh / HQ, h = bh % HQ;
    int hk = h / REP;
    int qstart = qb * 64;
    int tid = threadIdx.x, warp = tid >> 5, lane = tid & 31;

    uint32_t q_s = smem_u32(Qs);
    uint32_t k_s = smem_u32(Ks);
    uint32_t v_s = smem_u32(Vs);

    // load Q tile (64 x 128 fp16)
    {
        int row = tid >> 1, hf = tid & 1;
        const __half* src = g_q + ((size_t)(b*HQ + h) * S + qstart + row) * HD + hf * 64;
        uint32_t dQ = q_s + (uint32_t)((row * QPAD + hf * 64) * 2);
        #pragma unroll
        for (int j = 0; j < 8; j++)
            CP16(dQ + j*16, src + j*8);
        CP_COMMIT();
    }

    int g = lane >> 3;
    uint32_t a_off  = (uint32_t)((((g&1)*8 + (lane&7)) * QPAD + (g>>1)*8) * 2);
    uint32_t kb_off = (uint32_t)((((g>>1)*8 + (lane&7)) * QPAD + (g&1)*8) * 2);
    uint32_t vb_off = (uint32_t)(((lane&7) * VPAD + g*8) * 2);

    float o[16][4];
    #pragma unroll
    for (int i = 0; i < 16; i++)
        #pragma unroll
        for (int j = 0; j < 4; j++) o[i][j] = 0.f;
    float m0 = -1e30f, m1 = -1e30f, l0 = 0.f, l1 = 0.f;

    int kbeg = qstart - W; if (kbeg < 0) kbeg = 0;
    int kend = qstart + 64;
    const __half* Kg = g_k  + (size_t)(b*HKV + hk) * S * HD;
    const __half* Vg = g_vt + (size_t)(b*HKV + hk) * HD * S;

    int qrow0 = qstart + warp * 16 + (lane >> 2);

    for (int ks = kbeg; ks < kend; ks += 64) {
        __syncthreads();
        {   // K chunk (64 x 128 fp16) + V^T chunk (128 x 64 fp16) via cp.async
            int row = tid >> 1, hf = tid & 1;
            const __half* sK = Kg + (size_t)(ks + row) * HD + hf * 64;
            uint32_t dK = k_s + (uint32_t)((row * QPAD + hf * 64) * 2);
            #pragma unroll
            for (int j = 0; j < 8; j++)
                CP16(dK + j*16, sK + j*8);
            const __half* vS = Vg + (size_t)tid * S + ks;
            uint32_t eV = v_s + (uint32_t)(tid * VPAD * 2);
            #pragma unroll
            for (int j = 0; j < 8; j++)
                CP16(eV + j*16, vS + j*8);
            CP_COMMIT();
            CP_WAIT(0);
        }
        __syncthreads();

        // ---- scores = Q @ K^T (fp16 in, fp32 acc) ----
        float sc[8][4];
        #pragma unroll
        for (int nt = 0; nt < 8; nt++)
            #pragma unroll
            for (int e = 0; e < 4; e++) sc[nt][e] = 0.f;

        #pragma unroll
        for (int kk = 0; kk < 8; kk++) {
            uint32_t aF[4];
            ldsm4(aF, q_s + (uint32_t)((warp*16*QPAD + kk*16) * 2) + a_off);
            #pragma unroll
            for (int nt16 = 0; nt16 < 4; nt16++) {
                uint32_t bbf[4];
                ldsm4(bbf, k_s + (uint32_t)((nt16*16*QPAD + kk*16) * 2) + kb_off);
                mma16816h(sc[2*nt16],     aF, bbf[0], bbf[1]);
                mma16816h(sc[2*nt16 + 1], aF, bbf[2], bbf[3]);
            }
        }

        // ---- mask + online softmax (log2 domain; Q pre-scaled) ----
        #pragma unroll
        for (int nt = 0; nt < 8; nt++)
            #pragma unroll
            for (int e = 0; e < 4; e++) {
                int kp = ks + nt*8 + (lane & 3) * 2 + (e & 1);
                int qr = qrow0 + ((e >= 2) ? 8 : 0);
                if (kp < qr - W || kp > qr) sc[nt][e] = -1e30f;
            }
        float mx0 = -1e30f, mx1 = -1e30f;
        #pragma unroll
        for (int nt = 0; nt < 8; nt++) {
            mx0 = fmaxf(mx0, fmaxf(sc[nt][0], sc[nt][1]));
            mx1 = fmaxf(mx1, fmaxf(sc[nt][2], sc[nt][3]));
        }
        mx0 = fmaxf(mx0, __shfl_xor_sync(0xffffffffu, mx0, 1));
        mx0 = fmaxf(mx0, __shfl_xor_sync(0xffffffffu, mx0, 2));
        mx1 = fmaxf(mx1, __shfl_xor_sync(0xffffffffu, mx1, 1));
        mx1 = fmaxf(mx1, __shfl_xor_sync(0xffffffffu, mx1, 2));
        float mn0 = fmaxf(m0, mx0), mn1 = fmaxf(m1, mx1);
        float a0 = exp2f(m0 - mn0), a1 = exp2f(m1 - mn1);
        m0 = mn0; m1 = mn1;
        float s0 = 0.f, s1 = 0.f;
        #pragma unroll
        for (int nt = 0; nt < 8; nt++) {
            sc[nt][0] = exp2f(sc[nt][0] - mn0);
            sc[nt][1] = exp2f(sc[nt][1] - mn0);
            sc[nt][2] = exp2f(sc[nt][2] - mn1);
            sc[nt][3] = exp2f(sc[nt][3] - mn1);
            s0 += sc[nt][0] + sc[nt][1];
            s1 += sc[nt][2] + sc[nt][3];
        }
        s0 += __shfl_xor_sync(0xffffffffu, s0, 1);
        s0 += __shfl_xor_sync(0xffffffffu, s0, 2);
        s1 += __shfl_xor_sync(0xffffffffu, s1, 1);
        s1 += __shfl_xor_sync(0xffffffffu, s1, 2);
        l0 = l0 * a0 + s0;
        l1 = l1 * a1 + s1;
        #pragma unroll
        for (int dt = 0; dt < 16; dt++) {
            o[dt][0] *= a0; o[dt][1] *= a0;
            o[dt][2] *= a1; o[dt][3] *= a1;
        }

        // ---- O += P @ V (P fp16, V fp16) ----
        #pragma unroll
        for (int k2 = 0; k2 < 2; k2++) {
            uint32_t pF[2][4];
            #pragma unroll
            for (int q8 = 0; q8 < 2; q8++) {
                int nt = k2 * 4 + q8 * 2;
                pF[q8][0] = packh2(sc[nt][0],   sc[nt][1]);
                pF[q8][1] = packh2(sc[nt][2],   sc[nt][3]);
                pF[q8][2] = packh2(sc[nt+1][0], sc[nt+1][1]);
                pF[q8][3] = packh2(sc[nt+1][2], sc[nt+1][3]);
            }
            #pragma unroll
            for (int dt = 0; dt < 16; dt++) {
                uint32_t vv[4];
                ldsm4(vv, v_s + (uint32_t)((dt*8*VPAD + k2*32) * 2) + vb_off);
                mma16816h(o[dt], pF[0], vv[0], vv[1]);
                mma16816h(o[dt], pF[1], vv[2], vv[3]);
            }
        }
    }

    // ---- finalize, write fp16 attention output ------------------------------
    float inv0 = 1.f / l0, inv1 = 1.f / l1;
    #pragma unroll
    for (int dt = 0; dt < 16; dt++) {
        int d = dt * 8 + (lane & 3) * 2;
        size_t off0 = (size_t)(b * S + qrow0)     * D + h * HD + d;
        size_t off1 = (size_t)(b * S + qrow0 + 8) * D + h * HD + d;
        *(__half2*)(g_att + off0) = __floats2half2_rn(o[dt][0] * inv0, o[dt][1] * inv0);
        *(__half2*)(g_att + off1) = __floats2half2_rn(o[dt][2] * inv1, o[dt][3] * inv1);
    }
}

// ---------------- launch -------------------------------------------------------
extern "C" void kernel_launch(void* const* d_in, const int* in_sizes, int n_in,
                              void* d_out, int out_size) {
    const float* x  = (const float*)d_in[0];
    const float* g  = (const float*)d_in[1];
    const float* wq = (const float*)d_in[2];
    const float* wk = (const float*)d_in[3];
    const float* wv = (const float*)d_in[4];
    const float* wo = (const float*)d_in[5];
    float* out = (float*)d_out;

    void *xn, *wqkv, *wot, *qkvp, *att;
    cudaGetSymbolAddress(&xn, g_xn);
    cudaGetSymbolAddress(&wqkv, g_wqkvt);
    cudaGetSymbolAddress(&wot, g_wot);
    cudaGetSymbolAddress(&qkvp, g_qkvp);
    cudaGetSymbolAddress(&att, g_att);

    const int gemm_smem = 6 * GSTG;   // 61440 bytes (3 stages x A,B)
    cudaFuncSetAttribute(gemm_f16<true>,
                         cudaFuncAttributeMaxDynamicSharedMemorySize, gemm_smem);
    cudaFuncSetAttribute(gemm_f16<false>,
                         cudaFuncAttributeMaxDynamicSharedMemorySize, gemm_smem);
    const int attn_smem = (2 * 64 * QPAD + 128 * VPAD) * (int)sizeof(__half);  // 53248
    cudaFuncSetAttribute(attn_kernel,
                         cudaFuncAttributeMaxDynamicSharedMemorySize, attn_smem);

    // Launch order: profiler captures launch #4 -> QKV GEMM there.
    wconv_qkv_kernel<<<dim3(NQKV/32, D/32), dim3(32, 8)>>>(wq, wk, wv);        // 1
    rmsnorm_kernel<<<BS, 256>>>(x, g);                                         // 2
    rope_table_kernel<<<S, 64>>>();                                            // 3

    gemm_f16<true><<<dim3(NQKV/128, BS/128), 256, gemm_smem>>>(                // 4 <-- ncu
        (const __half*)xn, (const __half*)wqkv, qkvp, NQKV, D);

    wconv_kernel<<<dim3(D/32, D/32), dim3(32, 8)>>>(wo, (__half*)wot, D, D);   // 5
    rope_q_kernel<<<BS, 256>>>();                                              // 6
    rope_k_kernel<<<BS, 256>>>();                                              // 7
    vtrans_kernel<<<dim3(S/32, HD/32, B*HKV), dim3(32, 8)>>>();                // 8
    attn_kernel<<<dim3(S/64, B*HQ), 128, attn_smem>>>();                       // 9
    gemm_f16<false><<<dim3(D/128, BS/128), 256, gemm_smem>>>(                  // 10
        (const __half*)att, (const __half*)wot, out, D, D);
}